// round 8
// baseline (speedup 1.0000x reference)
#include <cuda_runtime.h>

#define TT   256   // timesteps
#define BB   512   // batch
#define NCTA 86    // CTAs (one per SM; 86*6 >= 512)
#define RR   6     // batch rows per CTA

typedef unsigned long long u64;

// Weight layout (per matrix), ulonglong2 index:
//   idx = (m*2 + qp)*512 + j*2 + ks     m in [0,64), qp in {0,1}, j in [0,256), ks in {0,1}
// contents (as 4 floats f0..f3):
//   f0 = W[q0][j][k0], f1 = W[q0][j][k1], f2 = W[q1][j][k0], f3 = W[q1][j][k1]
// with q0 = 2*qp, q1 = 2*qp+1, k0 = ks*128 + 2m, k1 = k0+1.
// => .x = packed (Wq0[k0], Wq0[k1]),  .y = packed (Wq1[k0], Wq1[k1])
// Padded +2048 for harmless prefetch overshoot.
__device__ ulonglong2 g_W1u [65536 + 2048];  // from W_hh1
__device__ ulonglong2 g_W2au[65536 + 2048];  // from W_ih2
__device__ ulonglong2 g_W2bu[65536 + 2048];  // from W_hh2

__global__ void prep_kernel(const float* __restrict__ Whh1,
                            const float* __restrict__ Wih2,
                            const float* __restrict__ Whh2) {
    int e = blockIdx.x * blockDim.x + threadIdx.x;
    if (e >= 256 * 256 * 4) return;
    int f    = e & 3;
    int idx  = e >> 2;
    int ks   = idx & 1;
    int j    = (idx >> 1) & 255;
    int qp   = (idx >> 9) & 1;
    int m    = idx >> 10;
    int q    = 2 * qp + (f >> 1);
    int k    = ks * 128 + 2 * m + (f & 1);
    int src  = (q * 256 + j) * 256 + k;
    reinterpret_cast<float*>(g_W1u)[e]  = Whh1[src];
    reinterpret_cast<float*>(g_W2au)[e] = Wih2[src];
    reinterpret_cast<float*>(g_W2bu)[e] = Whh2[src];
}

// ---- f32x2 packed helpers ----
__device__ __forceinline__ u64 pack2(float lo, float hi) {
    u64 r;
    asm("mov.b64 %0, {%1, %2};" : "=l"(r) : "f"(lo), "f"(hi));
    return r;
}
__device__ __forceinline__ void unpack2(u64 v, float& lo, float& hi) {
    asm("mov.b64 {%0, %1}, %2;" : "=f"(lo), "=f"(hi) : "l"(v));
}
__device__ __forceinline__ u64 ffma2(u64 a, u64 b, u64 c) {
    u64 d;
    asm("fma.rn.f32x2 %0, %1, %2, %3;" : "=l"(d) : "l"(a), "l"(b), "l"(c));
    return d;
}

__device__ __forceinline__ float sigmf(float x) {
    return __fdividef(1.0f, 1.0f + __expf(-x));
}
__device__ __forceinline__ float tanhf_fast(float x) {
    return __fdividef(2.0f, 1.0f + __expf(-2.0f * x)) - 1.0f;
}

// horizontal k-parity sum + cross-k-half (ks lanes adjacent) reduce
__device__ __forceinline__ float hsum2(u64 v) {
    float lo, hi;
    unpack2(v, lo, hi);
    float s = lo + hi;
    s += __shfl_xor_sync(0xffffffffu, s, 1);
    return s;
}

// h smem: float layer[2*128*12]; addr(ks,m,r,par) = ks*1536 + m*12 + r*2 + par
// holds h[r][k] with k = ks*128 + 2m + par. 16B chunk = rows(0,1) or (2,3) or (4,5)
// as u64 k-pairs.
#define HADDR(k, r) ((((k) >> 7) * 1536) + ((((k) & 127) >> 1) * 12) + ((r) * 2) + ((k) & 1))

// one m-step of one matrix: 1 (preloaded) weight ull2 + 3 LDS.128 -> 12 ffma2
__device__ __forceinline__ void mv_step(ulonglong2 w, const float* __restrict__ hb,
                                        int moff, u64* __restrict__ a0,
                                        u64* __restrict__ a1) {
    ulonglong2 hA = *reinterpret_cast<const ulonglong2*>(hb + moff);
    ulonglong2 hB = *reinterpret_cast<const ulonglong2*>(hb + moff + 4);
    ulonglong2 hC = *reinterpret_cast<const ulonglong2*>(hb + moff + 8);
    a0[0] = ffma2(w.x, hA.x, a0[0]);
    a0[1] = ffma2(w.x, hA.y, a0[1]);
    a0[2] = ffma2(w.x, hB.x, a0[2]);
    a0[3] = ffma2(w.x, hB.y, a0[3]);
    a0[4] = ffma2(w.x, hC.x, a0[4]);
    a0[5] = ffma2(w.x, hC.y, a0[5]);
    a1[0] = ffma2(w.y, hA.x, a1[0]);
    a1[1] = ffma2(w.y, hA.y, a1[1]);
    a1[2] = ffma2(w.y, hB.x, a1[2]);
    a1[3] = ffma2(w.y, hB.y, a1[3]);
    a1[4] = ffma2(w.y, hC.x, a1[4]);
    a1[5] = ffma2(w.y, hC.y, a1[5]);
}

__global__ void __launch_bounds__(1024) lstm_kernel(
    const float* __restrict__ x_in,   // (512,256,2)
    const float* __restrict__ W_ih1,  // (1024,2)
    const float* __restrict__ b_ih1, const float* __restrict__ b_hh1,
    const float* __restrict__ b_ih2, const float* __restrict__ b_hh2,
    const float* __restrict__ W_lin,  // (2,256)
    const float* __restrict__ b_lin,  // (2,)
    float* __restrict__ out)          // (512,256,2)
{
    __shared__ __align__(16) float sh1f[2 * 128 * 12];
    __shared__ __align__(16) float sh2f[2 * 128 * 12];
    __shared__ __align__(16) u64 exch[256 * 6];   // (j,r) -> packed (gate_g, gate_o)
    __shared__ float sh_x[RR][2];
    __shared__ float sh_wl[2][256];

    const int tid  = threadIdx.x;
    const int ks   = tid & 1;          // k-half
    const int j    = (tid >> 1) & 255; // hidden unit
    const int qp   = tid >> 9;         // 0: gates i,f   1: gates g,o
    const int b0   = blockIdx.x * RR;
    const int lane = tid & 31;
    const int warp = tid >> 5;

    // per-thread gate constants (gates 2qp, 2qp+1 of unit j)
    float bias1[2], bias2[2], wx0[2], wx1[2];
#pragma unroll
    for (int g = 0; g < 2; g++) {
        int row = (2 * qp + g) * 256 + j;
        bias1[g] = b_ih1[row] + b_hh1[row];
        bias2[g] = b_ih2[row] + b_hh2[row];
        wx0[g] = W_ih1[row * 2 + 0];
        wx1[g] = W_ih1[row * 2 + 1];
    }
    if (qp == 0 && ks == 0) {
        sh_wl[0][j] = W_lin[j];
        sh_wl[1][j] = W_lin[256 + j];
    }
    for (int i = tid; i < 2 * 128 * 12; i += 1024) { sh1f[i] = 0.0f; sh2f[i] = 0.0f; }

    float c1[4], c2[4];   // ks0: rows 0-3 ; ks1: rows 4,5 (slots 0,1)
#pragma unroll
    for (int r = 0; r < 4; r++) { c1[r] = 0.0f; c2[r] = 0.0f; }

    const int woff = qp * 512 + j * 2 + ks;
    const float* hb1 = sh1f + ks * 1536;
    const float* hb2 = sh2f + ks * 1536;
    // h write address pieces for unit j (qp==0 threads write h)
    const int hwbase = ((j >> 7) * 1536) + (((j & 127) >> 1) * 12) + (j & 1);

    for (int t = 0; t < TT; t++) {
        // prefetch layer-1 weights BEFORE the barrier (independent of smem)
        const ulonglong2* wp = g_W1u + woff;
        ulonglong2 w0 = __ldg(wp);
        ulonglong2 w1 = __ldg(wp + 1024);
        wp += 2048;

        if (tid < RR * 2) {
            int r = tid >> 1, c = tid & 1;
            int b = b0 + r;
            sh_x[r][c] = (b < BB) ? x_in[(b * TT + t) * 2 + c] : 0.0f;
        }
        __syncthreads();  // (A) x visible; prev-step buffer reads complete

        u64 a0[6], a1[6];
#pragma unroll
        for (int r = 0; r < 6; r++) { a0[r] = 0ULL; a1[r] = 0ULL; }

        // ===== layer 1 matvec: h1 * Whh1^T =====
        for (int m = 0; m < 64; m += 2) {
            ulonglong2 w2 = __ldg(wp);
            ulonglong2 w3 = __ldg(wp + 1024);
            wp += 2048;
            mv_step(w0, hb1, m * 12, a0, a1);
            mv_step(w1, hb1, m * 12 + 12, a0, a1);
            w0 = w2; w1 = w3;
        }

        // prefetch layer-2 weights now (hidden under epilogue + 2 barriers)
        const ulonglong2* wpa = g_W2au + woff;
        const ulonglong2* wpb = g_W2bu + woff;
        ulonglong2 wa = __ldg(wpa);
        ulonglong2 wb = __ldg(wpb);
        wpa += 1024; wpb += 1024;

        // epilogue 1: reduce + bias + x-term
        float gate0[6], gate1[6];
#pragma unroll
        for (int r = 0; r < 6; r++) {
            float x0 = sh_x[r][0], x1 = sh_x[r][1];
            gate0[r] = hsum2(a0[r]) + fmaf(x1, wx1[0], fmaf(x0, wx0[0], bias1[0]));
            gate1[r] = hsum2(a1[r]) + fmaf(x1, wx1[1], fmaf(x0, wx0[1], bias1[1]));
        }
        if (qp == 1) {  // publish (g,o)
            if (ks == 0) {
#pragma unroll
                for (int r = 0; r < 4; r++) exch[j * 6 + r] = pack2(gate0[r], gate1[r]);
            } else {
#pragma unroll
                for (int r = 4; r < 6; r++) exch[j * 6 + r] = pack2(gate0[r], gate1[r]);
            }
        }
        __syncthreads();  // (B) exch full; sh1 reads done
        if (qp == 0) {    // cell + write h1
            if (ks == 0) {
#pragma unroll
                for (int r = 0; r < 4; r++) {
                    float gg, go;
                    unpack2(exch[j * 6 + r], gg, go);
                    c1[r] = sigmf(gate1[r]) * c1[r] + sigmf(gate0[r]) * tanhf_fast(gg);
                    sh1f[hwbase + r * 2] = sigmf(go) * tanhf_fast(c1[r]);
                }
            } else {
#pragma unroll
                for (int r = 4; r < 6; r++) {
                    float gg, go;
                    unpack2(exch[j * 6 + r], gg, go);
                    c1[r - 4] = sigmf(gate1[r]) * c1[r - 4] + sigmf(gate0[r]) * tanhf_fast(gg);
                    sh1f[hwbase + r * 2] = sigmf(go) * tanhf_fast(c1[r - 4]);
                }
            }
        }
        __syncthreads();  // (C) new h1 visible

#pragma unroll
        for (int r = 0; r < 6; r++) { a0[r] = 0ULL; a1[r] = 0ULL; }

        // ===== layer 2 matvec: h1 * Wih2^T + h2 * Whh2^T =====
        for (int m = 0; m < 64; m++) {
            ulonglong2 wa1 = __ldg(wpa);
            ulonglong2 wb1 = __ldg(wpb);
            wpa += 1024; wpb += 1024;
            mv_step(wa, hb1, m * 12, a0, a1);
            mv_step(wb, hb2, m * 12, a0, a1);
            wa = wa1; wb = wb1;
        }

        // epilogue 2: reduce + bias
#pragma unroll
        for (int r = 0; r < 6; r++) {
            gate0[r] = hsum2(a0[r]) + bias2[0];
            gate1[r] = hsum2(a1[r]) + bias2[1];
        }
        if (qp == 1) {
            if (ks == 0) {
#pragma unroll
                for (int r = 0; r < 4; r++) exch[j * 6 + r] = pack2(gate0[r], gate1[r]);
            } else {
#pragma unroll
                for (int r = 4; r < 6; r++) exch[j * 6 + r] = pack2(gate0[r], gate1[r]);
            }
        }
        __syncthreads();  // (D) exch full; sh1/sh2 reads done
        if (qp == 0) {    // cell + write h2
            if (ks == 0) {
#pragma unroll
                for (int r = 0; r < 4; r++) {
                    float gg, go;
                    unpack2(exch[j * 6 + r], gg, go);
                    c2[r] = sigmf(gate1[r]) * c2[r] + sigmf(gate0[r]) * tanhf_fast(gg);
                    sh2f[hwbase + r * 2] = sigmf(go) * tanhf_fast(c2[r]);
                }
            } else {
#pragma unroll
                for (int r = 4; r < 6; r++) {
                    float gg, go;
                    unpack2(exch[j * 6 + r], gg, go);
                    c2[r - 4] = sigmf(gate1[r]) * c2[r - 4] + sigmf(gate0[r]) * tanhf_fast(gg);
                    sh2f[hwbase + r * 2] = sigmf(go) * tanhf_fast(c2[r - 4]);
                }
            }
        }
        __syncthreads();  // (E) new h2 visible

        // ===== y = h2 * W_lin^T + b_lin : warp r -> batch row r =====
        if (warp < RR) {
            int r = warp;
            int b = b0 + r;
            if (b < BB) {
                float s0 = 0.0f, s1 = 0.0f;
#pragma unroll
                for (int mm = 0; mm < 8; mm++) {
                    int k = lane + mm * 32;
                    float h = sh2f[HADDR(k, r)];
                    s0 = fmaf(sh_wl[0][k], h, s0);
                    s1 = fmaf(sh_wl[1][k], h, s1);
                }
#pragma unroll
                for (int off = 16; off; off >>= 1) {
                    s0 += __shfl_xor_sync(0xffffffffu, s0, off);
                    s1 += __shfl_xor_sync(0xffffffffu, s1, off);
                }
                if (lane == 0) {
                    out[(b * TT + t) * 2 + 0] = s0 + b_lin[0];
                    out[(b * TT + t) * 2 + 1] = s1 + b_lin[1];
                }
            }
        }
        // next iteration's sync (A) orders buffer reuse
    }
}

extern "C" void kernel_launch(void* const* d_in, const int* in_sizes, int n_in,
                              void* d_out, int out_size) {
    const float* inputs = (const float*)d_in[0];
    const float* W_ih1  = (const float*)d_in[1];
    const float* W_hh1  = (const float*)d_in[2];
    const float* b_ih1  = (const float*)d_in[3];
    const float* b_hh1  = (const float*)d_in[4];
    const float* W_ih2  = (const float*)d_in[5];
    const float* W_hh2  = (const float*)d_in[6];
    const float* b_ih2  = (const float*)d_in[7];
    const float* b_hh2  = (const float*)d_in[8];
    const float* W_lin  = (const float*)d_in[9];
    const float* b_lin  = (const float*)d_in[10];

    prep_kernel<<<1024, 256>>>(W_hh1, W_ih2, W_hh2);
    lstm_kernel<<<NCTA, 1024>>>(inputs, W_ih1, b_ih1, b_hh1, b_ih2, b_hh2,
                                W_lin, b_lin, (float*)d_out);
}

// round 9
// speedup vs baseline: 1.6151x; 1.6151x over previous
#include <cuda_runtime.h>

#define TT   256   // timesteps
#define BB   512   // batch
#define NCTA 86    // CTAs (one per SM; 86*6 >= 512)
#define RR   6     // batch rows per CTA

typedef unsigned long long u64;

// Weight layout (per matrix), ulonglong2 index:
//   idx = (m*2 + qp)*256 + j      m in [0,128), qp in {0,1}, j in [0,256)
// float element f of that ull2:
//   q = 2*qp + (f>>1),  k = 2*m + (f&1)
//   value = W_orig[(q*256+j)*256 + k]
// => .x = packed (Wq0[k0], Wq0[k1]),  .y = packed (Wq1[k0], Wq1[k1])
// Padded +1024 ull2 for prefetch overshoot.
__device__ ulonglong2 g_W1u [65536 + 1024];  // from W_hh1
__device__ ulonglong2 g_W2au[65536 + 1024];  // from W_ih2
__device__ ulonglong2 g_W2bu[65536 + 1024];  // from W_hh2

__global__ void prep_kernel(const float* __restrict__ Whh1,
                            const float* __restrict__ Wih2,
                            const float* __restrict__ Whh2) {
    int e = blockIdx.x * blockDim.x + threadIdx.x;
    if (e >= 256 * 256 * 4) return;
    int f   = e & 3;
    int idx = e >> 2;
    int j   = idx & 255;
    int qp  = (idx >> 8) & 1;
    int m   = idx >> 9;
    int q   = 2 * qp + (f >> 1);
    int k   = 2 * m + (f & 1);
    int src = (q * 256 + j) * 256 + k;
    reinterpret_cast<float*>(g_W1u)[e]  = Whh1[src];
    reinterpret_cast<float*>(g_W2au)[e] = Wih2[src];
    reinterpret_cast<float*>(g_W2bu)[e] = Whh2[src];
}

// ---- f32x2 packed helpers ----
__device__ __forceinline__ u64 pack2(float lo, float hi) {
    u64 r;
    asm("mov.b64 %0, {%1, %2};" : "=l"(r) : "f"(lo), "f"(hi));
    return r;
}
__device__ __forceinline__ void unpack2(u64 v, float& lo, float& hi) {
    asm("mov.b64 {%0, %1}, %2;" : "=f"(lo), "=f"(hi) : "l"(v));
}
__device__ __forceinline__ u64 ffma2(u64 a, u64 b, u64 c) {
    u64 d;
    asm("fma.rn.f32x2 %0, %1, %2, %3;" : "=l"(d) : "l"(a), "l"(b), "l"(c));
    return d;
}

__device__ __forceinline__ float sigmf(float x) {
    return __fdividef(1.0f, 1.0f + __expf(-x));
}
__device__ __forceinline__ float tanhf_fast(float x) {
    return __fdividef(2.0f, 1.0f + __expf(-2.0f * x)) - 1.0f;
}

// horizontal sum of the two packed k-parity partials
__device__ __forceinline__ float hsum(u64 v) {
    float lo, hi;
    unpack2(v, lo, hi);
    return lo + hi;
}

// h smem layout: float sh[128][6][2]; addr(k, r) = (k>>1)*12 + r*2 + (k&1)
// 48B per 2k-group = 3 LDS.128 per m-iter, single address across the warp (broadcast).
#define HADDR(k, r) ((((k) >> 1) * 12) + ((r) * 2) + ((k) & 1))

// one m-step of one matrix: 1 weight ull2 (preloaded) + 3 LDS.128 -> 12 ffma2
__device__ __forceinline__ void mv_step(ulonglong2 w, const float* __restrict__ hb,
                                        int m, u64* __restrict__ a0,
                                        u64* __restrict__ a1) {
    ulonglong2 H0 = *reinterpret_cast<const ulonglong2*>(hb + m * 12);
    ulonglong2 H1 = *reinterpret_cast<const ulonglong2*>(hb + m * 12 + 4);
    ulonglong2 H2 = *reinterpret_cast<const ulonglong2*>(hb + m * 12 + 8);
    a0[0] = ffma2(w.x, H0.x, a0[0]);
    a0[1] = ffma2(w.x, H0.y, a0[1]);
    a0[2] = ffma2(w.x, H1.x, a0[2]);
    a0[3] = ffma2(w.x, H1.y, a0[3]);
    a0[4] = ffma2(w.x, H2.x, a0[4]);
    a0[5] = ffma2(w.x, H2.y, a0[5]);
    a1[0] = ffma2(w.y, H0.x, a1[0]);
    a1[1] = ffma2(w.y, H0.y, a1[1]);
    a1[2] = ffma2(w.y, H1.x, a1[2]);
    a1[3] = ffma2(w.y, H1.y, a1[3]);
    a1[4] = ffma2(w.y, H2.x, a1[4]);
    a1[5] = ffma2(w.y, H2.y, a1[5]);
}

__global__ void __launch_bounds__(512) lstm_kernel(
    const float* __restrict__ x_in,   // (512,256,2)
    const float* __restrict__ W_ih1,  // (1024,2)
    const float* __restrict__ b_ih1, const float* __restrict__ b_hh1,
    const float* __restrict__ b_ih2, const float* __restrict__ b_hh2,
    const float* __restrict__ W_lin,  // (2,256)
    const float* __restrict__ b_lin,  // (2,)
    float* __restrict__ out)          // (512,256,2)
{
    __shared__ __align__(16) float sh1f[128 * 12];
    __shared__ __align__(16) float sh2f[128 * 12];
    __shared__ __align__(16) u64 exch[256 * 7];   // stride 7 to spread banks
    __shared__ float sh_x[2][RR][2];              // double-buffered x_t
    __shared__ float sh_wl[2][256];

    const int tid  = threadIdx.x;
    const int j    = tid & 255;     // hidden unit
    const int qp   = tid >> 8;      // 0: gates i,f   1: gates g,o
    const int b0   = blockIdx.x * RR;
    const int lane = tid & 31;
    const int warp = tid >> 5;

    // per-thread gate constants (gates 2qp, 2qp+1 of unit j)
    float bias1[2], bias2[2], wx0[2], wx1[2];
#pragma unroll
    for (int g = 0; g < 2; g++) {
        int row = (2 * qp + g) * 256 + j;
        bias1[g] = b_ih1[row] + b_hh1[row];
        bias2[g] = b_ih2[row] + b_hh2[row];
        wx0[g] = W_ih1[row * 2 + 0];
        wx1[g] = W_ih1[row * 2 + 1];
    }
    if (qp == 0) {
        sh_wl[0][j] = W_lin[j];
        sh_wl[1][j] = W_lin[256 + j];
    }
    for (int i = tid; i < 128 * 12; i += 512) { sh1f[i] = 0.0f; sh2f[i] = 0.0f; }
    // stage x for t=0 into buffer 0
    if (tid < RR * 2) {
        int r = tid >> 1, c = tid & 1;
        int b = b0 + r;
        sh_x[0][r][c] = (b < BB) ? x_in[(b * TT + 0) * 2 + c] : 0.0f;
    }

    float c1[RR], c2[RR];
#pragma unroll
    for (int r = 0; r < RR; r++) { c1[r] = 0.0f; c2[r] = 0.0f; }

    const float blin0 = b_lin[0], blin1 = b_lin[1];
    const int woff   = qp * 256 + j;
    const int hwbase = ((j >> 1) * 12) + (j & 1);   // + r*2 for row r

    __syncthreads();

    for (int t = 0; t < TT; t++) {
        u64 a0[6], a1[6];
#pragma unroll
        for (int r = 0; r < 6; r++) { a0[r] = 0ULL; a1[r] = 0ULL; }

        // ===== layer 1 matvec: h1 * Whh1^T (2-deep weight rotation) =====
        {
            const ulonglong2* wp = g_W1u + woff;
            ulonglong2 w0 = __ldg(wp);
            ulonglong2 w1 = __ldg(wp + 512);
            wp += 1024;
            for (int m = 0; m < 128; m += 2) {
                ulonglong2 w2 = __ldg(wp);
                ulonglong2 w3 = __ldg(wp + 512);
                wp += 1024;
                mv_step(w0, sh1f, m, a0, a1);
                mv_step(w1, sh1f, m + 1, a0, a1);
                w0 = w2; w1 = w3;
            }
        }

        // epilogue 1: reduce k-parity + bias + x-term
        float s0[6], s1[6];
        {
            const float (*xb)[2] = sh_x[t & 1];
#pragma unroll
            for (int r = 0; r < 6; r++) {
                float x0 = xb[r][0], x1 = xb[r][1];
                s0[r] = hsum(a0[r]) + fmaf(x1, wx1[0], fmaf(x0, wx0[0], bias1[0]));
                s1[r] = hsum(a1[r]) + fmaf(x1, wx1[1], fmaf(x0, wx0[1], bias1[1]));
            }
        }
        if (qp == 1) {  // publish (g,o)
#pragma unroll
            for (int r = 0; r < 6; r++) exch[j * 7 + r] = pack2(s0[r], s1[r]);
        }

        // prefetch layer-2 weights BEFORE the barrier (latency hidden by B + cell1)
        const ulonglong2* wpa = g_W2au + woff;
        const ulonglong2* wpb = g_W2bu + woff;
        ulonglong2 wa0 = __ldg(wpa), wa1 = __ldg(wpa + 512);
        ulonglong2 wb0 = __ldg(wpb), wb1 = __ldg(wpb + 512);
        wpa += 1024; wpb += 1024;

        __syncthreads();  // (B) exch full; sh1 reads done

        if (qp == 0) {    // cell 1: i=s0, f=s1, (g,o) from exch
#pragma unroll
            for (int r = 0; r < 6; r++) {
                float gg, go;
                unpack2(exch[j * 7 + r], gg, go);
                c1[r] = sigmf(s1[r]) * c1[r] + sigmf(s0[r]) * tanhf_fast(gg);
                sh1f[hwbase + r * 2] = sigmf(go) * tanhf_fast(c1[r]);
            }
        } else if (tid < 256 + RR * 2 && t + 1 < TT) {
            // qp1 threads idle here: stage x for t+1
            int r = (tid - 256) >> 1, c = tid & 1;
            int b = b0 + r;
            sh_x[(t + 1) & 1][r][c] = (b < BB) ? x_in[(b * TT + t + 1) * 2 + c] : 0.0f;
        }
        __syncthreads();  // (C) new h1 visible

#pragma unroll
        for (int r = 0; r < 6; r++) { a0[r] = 0ULL; a1[r] = 0ULL; }

        // ===== layer 2 matvec: h1 * Wih2^T + h2 * Whh2^T =====
        for (int m = 0; m < 128; m += 2) {
            ulonglong2 wa2 = __ldg(wpa), wa3 = __ldg(wpa + 512);
            ulonglong2 wb2 = __ldg(wpb), wb3 = __ldg(wpb + 512);
            wpa += 1024; wpb += 1024;
            mv_step(wa0, sh1f, m, a0, a1);
            mv_step(wb0, sh2f, m, a0, a1);
            mv_step(wa1, sh1f, m + 1, a0, a1);
            mv_step(wb1, sh2f, m + 1, a0, a1);
            wa0 = wa2; wa1 = wa3; wb0 = wb2; wb1 = wb3;
        }

        // epilogue 2
#pragma unroll
        for (int r = 0; r < 6; r++) {
            s0[r] = hsum(a0[r]) + bias2[0];
            s1[r] = hsum(a1[r]) + bias2[1];
        }
        if (qp == 1) {
#pragma unroll
            for (int r = 0; r < 6; r++) exch[j * 7 + r] = pack2(s0[r], s1[r]);
        }
        __syncthreads();  // (D) exch full; sh1/sh2 reads done

        if (qp == 0) {    // cell 2
#pragma unroll
            for (int r = 0; r < 6; r++) {
                float gg, go;
                unpack2(exch[j * 7 + r], gg, go);
                c2[r] = sigmf(s1[r]) * c2[r] + sigmf(s0[r]) * tanhf_fast(gg);
                sh2f[hwbase + r * 2] = sigmf(go) * tanhf_fast(c2[r]);
            }
        }
        __syncthreads();  // (E) new h2 visible

        // ===== y = h2 * W_lin^T + b_lin : warp r -> batch row r =====
        if (warp < RR) {
            int r = warp;
            int b = b0 + r;
            if (b < BB) {
                float v0 = 0.0f, v1 = 0.0f;
#pragma unroll
                for (int mm = 0; mm < 8; mm++) {
                    int k = lane + mm * 32;
                    float h = sh2f[HADDR(k, r)];
                    v0 = fmaf(sh_wl[0][k], h, v0);
                    v1 = fmaf(sh_wl[1][k], h, v1);
                }
#pragma unroll
                for (int off = 16; off; off >>= 1) {
                    v0 += __shfl_xor_sync(0xffffffffu, v0, off);
                    v1 += __shfl_xor_sync(0xffffffffu, v1, off);
                }
                if (lane == 0) {
                    out[(b * TT + t) * 2 + 0] = v0 + blin0;
                    out[(b * TT + t) * 2 + 1] = v1 + blin1;
                }
            }
        }
        // next step's barrier (B) orders all buffer reuse
    }
}

extern "C" void kernel_launch(void* const* d_in, const int* in_sizes, int n_in,
                              void* d_out, int out_size) {
    const float* inputs = (const float*)d_in[0];
    const float* W_ih1  = (const float*)d_in[1];
    const float* W_hh1  = (const float*)d_in[2];
    const float* b_ih1  = (const float*)d_in[3];
    const float* b_hh1  = (const float*)d_in[4];
    const float* W_ih2  = (const float*)d_in[5];
    const float* W_hh2  = (const float*)d_in[6];
    const float* b_ih2  = (const float*)d_in[7];
    const float* b_hh2  = (const float*)d_in[8];
    const float* W_lin  = (const float*)d_in[9];
    const float* b_lin  = (const float*)d_in[10];

    prep_kernel<<<1024, 256>>>(W_hh1, W_ih2, W_hh2);
    lstm_kernel<<<NCTA, 512>>>(inputs, W_ih1, b_ih1, b_hh1, b_ih2, b_hh2,
                               W_lin, b_lin, (float*)d_out);
}